// round 2
// baseline (speedup 1.0000x reference)
#include <cuda_runtime.h>
#include <cuda_bf16.h>
#include <mma.h>
#include <cstdint>

using namespace nvcuda;

#define BATCH 2
#define SEQ   8192
#define DIMC  1024
#define NH    16
#define HD    64
#define CHUNK 128
#define NT    64
#define NROWS 16384
#define QKVN  3072
#define SCALE_ATTN 0.125f
#define EPS_BIT 1.1920929e-07f
#define EPS_OUT 1e-06f

// ---------------- static device scratch (no allocations allowed) ----------------
__device__ __nv_bfloat16 g_xq[(size_t)NROWS * DIMC];
__device__ float         g_adeq[NROWS];
__device__ __nv_bfloat16 g_wq_qkv[(size_t)QKVN * DIMC];
__device__ __nv_bfloat16 g_wq_proj[(size_t)DIMC * DIMC];
__device__ float         g_wdeq[2];
__device__ float         g_part[256];
__device__ float         g_qkv[(size_t)NROWS * QKVN];
__device__ float         g_q[(size_t)BATCH * NH * NT * CHUNK * HD];
__device__ float         g_k[(size_t)BATCH * NH * NT * CHUNK * HD];
__device__ float         g_v[(size_t)BATCH * NH * NT * CHUNK * HD];
__device__ float         g_kvsum[(size_t)BATCH * NH * NT * HD * HD];
__device__ float         g_kvpre[(size_t)BATCH * NH * NT * HD * HD];
__device__ float         g_attn[(size_t)NROWS * DIMC];
__device__ __nv_bfloat16 g_xq2[(size_t)NROWS * DIMC];
__device__ float         g_adeq2[NROWS];

// ---------------- fast exp (FMA poly, avoids MUFU bottleneck) ----------------
__device__ __forceinline__ float fexp(float x) {
    x = fmaxf(x, -80.0f);
    float y = x * 1.4426950408889634f;
    float n = rintf(y);
    float g = fmaf(-n, 0.6931471805599453f, x);   // x - n*ln2, |g| <= 0.347
    float p = 1.9841270e-4f;                       // 1/5040
    p = fmaf(p, g, 1.3888889e-3f);
    p = fmaf(p, g, 8.3333333e-3f);
    p = fmaf(p, g, 4.1666667e-2f);
    p = fmaf(p, g, 1.6666667e-1f);
    p = fmaf(p, g, 5.0e-1f);
    p = fmaf(p, g, 1.0f);
    p = fmaf(p, g, 1.0f);
    float s = __int_as_float(((int)n + 127) << 23);
    return p * s;
}

// ---------------- weight quant: mean(|w|) two-stage, then ternarize ----------------
__global__ void absmean_partial(const float* __restrict__ w, int n) {
    __shared__ float red[256];
    int tid = threadIdx.x;
    float s = 0.f;
    for (int i = blockIdx.x * 256 + tid; i < n; i += 65536) s += fabsf(w[i]);
    red[tid] = s; __syncthreads();
    for (int st = 128; st > 0; st >>= 1) { if (tid < st) red[tid] += red[tid + st]; __syncthreads(); }
    if (tid == 0) g_part[blockIdx.x] = red[0];
}

__global__ void absmean_final(int n, int slot) {
    __shared__ float red[256];
    int tid = threadIdx.x;
    red[tid] = g_part[tid]; __syncthreads();
    for (int st = 128; st > 0; st >>= 1) { if (tid < st) red[tid] += red[tid + st]; __syncthreads(); }
    if (tid == 0) g_wdeq[slot] = fmaxf(red[0] / (float)n, 1e-5f);
}

__global__ void quant_weight(const float* __restrict__ w, __nv_bfloat16* __restrict__ wq,
                             int n, int slot) {
    float s = 1.0f / g_wdeq[slot];
    for (int i = blockIdx.x * blockDim.x + threadIdx.x; i < n; i += gridDim.x * blockDim.x) {
        float v = rintf(w[i] * s);
        v = fminf(fmaxf(v, -1.f), 1.f);
        wq[i] = __float2bfloat16(v);
    }
}

// ---------------- activation quant for QKV input: RMS(EPS_BIT)*nw -> int8 fakequant ----------------
__global__ void __launch_bounds__(256) act_quant_x(const float* __restrict__ x,
                                                   const float* __restrict__ nw) {
    __shared__ float red[256];
    __shared__ float bc;
    int row = blockIdx.x, tid = threadIdx.x;
    float4 xv = ((const float4*)(x + (size_t)row * DIMC))[tid];
    float4 wv = ((const float4*)nw)[tid];
    float ss = xv.x*xv.x + xv.y*xv.y + xv.z*xv.z + xv.w*xv.w;
    red[tid] = ss; __syncthreads();
    for (int st = 128; st > 0; st >>= 1) { if (tid < st) red[tid] += red[tid + st]; __syncthreads(); }
    if (tid == 0) bc = rsqrtf(red[0] * (1.0f / DIMC) + EPS_BIT);
    __syncthreads();
    float r = bc;
    float n0 = xv.x*r*wv.x, n1 = xv.y*r*wv.y, n2 = xv.z*r*wv.z, n3 = xv.w*r*wv.w;
    float amax = fmaxf(fmaxf(fabsf(n0), fabsf(n1)), fmaxf(fabsf(n2), fabsf(n3)));
    red[tid] = amax; __syncthreads();
    for (int st = 128; st > 0; st >>= 1) { if (tid < st) red[tid] = fmaxf(red[tid], red[tid + st]); __syncthreads(); }
    if (tid == 0) {
        float mx = fmaxf(red[0], 1e-5f);
        bc = 127.0f / mx;
        g_adeq[row] = mx * (1.0f / 127.0f);
    }
    __syncthreads();
    float sc = bc;
    __nv_bfloat16* out = g_xq + (size_t)row * DIMC + tid * 4;
    out[0] = __float2bfloat16(fminf(fmaxf(rintf(n0 * sc), -128.f), 127.f));
    out[1] = __float2bfloat16(fminf(fmaxf(rintf(n1 * sc), -128.f), 127.f));
    out[2] = __float2bfloat16(fminf(fmaxf(rintf(n2 * sc), -128.f), 127.f));
    out[3] = __float2bfloat16(fminf(fmaxf(rintf(n3 * sc), -128.f), 127.f));
}

// ---------------- double-norm + act quant for proj input ----------------
__global__ void __launch_bounds__(256) norm2_quant(const float* __restrict__ nw,
                                                   const float* __restrict__ pnw) {
    __shared__ float red[256];
    __shared__ float bc;
    int row = blockIdx.x, tid = threadIdx.x;
    float4 xv = ((const float4*)(g_attn + (size_t)row * DIMC))[tid];
    float4 wv = ((const float4*)nw)[tid];
    float4 pv = ((const float4*)pnw)[tid];
    float ss = xv.x*xv.x + xv.y*xv.y + xv.z*xv.z + xv.w*xv.w;
    red[tid] = ss; __syncthreads();
    for (int st = 128; st > 0; st >>= 1) { if (tid < st) red[tid] += red[tid + st]; __syncthreads(); }
    if (tid == 0) bc = rsqrtf(red[0] * (1.0f / DIMC) + EPS_OUT);
    __syncthreads();
    float r1 = bc;
    float z0 = xv.x*r1*wv.x, z1 = xv.y*r1*wv.y, z2 = xv.z*r1*wv.z, z3 = xv.w*r1*wv.w;
    float ss2 = z0*z0 + z1*z1 + z2*z2 + z3*z3;
    red[tid] = ss2; __syncthreads();
    for (int st = 128; st > 0; st >>= 1) { if (tid < st) red[tid] += red[tid + st]; __syncthreads(); }
    if (tid == 0) bc = rsqrtf(red[0] * (1.0f / DIMC) + EPS_BIT);
    __syncthreads();
    float r2 = bc;
    float n0 = z0*r2*pv.x, n1 = z1*r2*pv.y, n2 = z2*r2*pv.z, n3 = z3*r2*pv.w;
    float amax = fmaxf(fmaxf(fabsf(n0), fabsf(n1)), fmaxf(fabsf(n2), fabsf(n3)));
    red[tid] = amax; __syncthreads();
    for (int st = 128; st > 0; st >>= 1) { if (tid < st) red[tid] = fmaxf(red[tid], red[tid + st]); __syncthreads(); }
    if (tid == 0) {
        float mx = fmaxf(red[0], 1e-5f);
        bc = 127.0f / mx;
        g_adeq2[row] = mx * (1.0f / 127.0f);
    }
    __syncthreads();
    float sc = bc;
    __nv_bfloat16* out = g_xq2 + (size_t)row * DIMC + tid * 4;
    out[0] = __float2bfloat16(fminf(fmaxf(rintf(n0 * sc), -128.f), 127.f));
    out[1] = __float2bfloat16(fminf(fmaxf(rintf(n1 * sc), -128.f), 127.f));
    out[2] = __float2bfloat16(fminf(fmaxf(rintf(n2 * sc), -128.f), 127.f));
    out[3] = __float2bfloat16(fminf(fmaxf(rintf(n3 * sc), -128.f), 127.f));
}

// ---------------- bf16 WMMA GEMM: out[M,N] = A[M,1024] @ W[N,1024]^T * (adeq*wdeq) + bias ----------------
#define AS_LD 48
#define CS_LD 20
__global__ void __launch_bounds__(256) gemm_bf16(
    const __nv_bfloat16* __restrict__ A, const __nv_bfloat16* __restrict__ W,
    float* __restrict__ C, int N,
    const float* __restrict__ adeq, int wslot, const float* __restrict__ bias)
{
    __shared__ __align__(16) __nv_bfloat16 As[128 * AS_LD];
    __shared__ __align__(16) __nv_bfloat16 Bs[64 * AS_LD];
    __shared__ __align__(16) float Cs[8 * 16 * CS_LD];

    int tid = threadIdx.x;
    int wid = tid >> 5, lane = tid & 31;
    int wm = wid >> 1, wn = wid & 1;
    int bm = blockIdx.y * 128;
    int bn = blockIdx.x * 64;
    float wdeq = g_wdeq[wslot];

    wmma::fragment<wmma::accumulator, 16, 16, 16, float> c[2][2];
    #pragma unroll
    for (int i = 0; i < 2; i++)
        #pragma unroll
        for (int j = 0; j < 2; j++) wmma::fill_fragment(c[i][j], 0.0f);

    int arow = tid >> 1, ahalf = (tid & 1) * 16;
    int brow = tid >> 2, bpart = (tid & 3) * 8;
    const __nv_bfloat16* Ag = A + (size_t)(bm + arow) * 1024 + ahalf;
    const __nv_bfloat16* Bg = W + (size_t)(bn + brow) * 1024 + bpart;

    for (int kt = 0; kt < 1024; kt += 32) {
        uint4 a0 = *(const uint4*)(Ag + kt);
        uint4 a1 = *(const uint4*)(Ag + kt + 8);
        uint4 b0 = *(const uint4*)(Bg + kt);
        *(uint4*)(&As[arow * AS_LD + ahalf])     = a0;
        *(uint4*)(&As[arow * AS_LD + ahalf + 8]) = a1;
        *(uint4*)(&Bs[brow * AS_LD + bpart])     = b0;
        __syncthreads();
        #pragma unroll
        for (int kk = 0; kk < 32; kk += 16) {
            wmma::fragment<wmma::matrix_a, 16, 16, 16, __nv_bfloat16, wmma::row_major> af[2];
            wmma::fragment<wmma::matrix_b, 16, 16, 16, __nv_bfloat16, wmma::col_major> bf[2];
            #pragma unroll
            for (int i = 0; i < 2; i++)
                wmma::load_matrix_sync(af[i], &As[(wm * 32 + i * 16) * AS_LD + kk], AS_LD);
            #pragma unroll
            for (int j = 0; j < 2; j++)
                wmma::load_matrix_sync(bf[j], &Bs[(wn * 32 + j * 16) * AS_LD + kk], AS_LD);
            #pragma unroll
            for (int i = 0; i < 2; i++)
                #pragma unroll
                for (int j = 0; j < 2; j++)
                    wmma::mma_sync(c[i][j], af[i], bf[j], c[i][j]);
        }
        __syncthreads();
    }

    float* Csw = &Cs[wid * 16 * CS_LD];
    #pragma unroll
    for (int i = 0; i < 2; i++) {
        #pragma unroll
        for (int j = 0; j < 2; j++) {
            __syncwarp();
            wmma::store_matrix_sync(Csw, c[i][j], CS_LD, wmma::mem_row_major);
            __syncwarp();
            int r  = lane >> 1;
            int cc = (lane & 1) * 8;
            int grow = bm + wm * 32 + i * 16 + r;
            int gcol = bn + wn * 32 + j * 16 + cc;
            float sc = adeq[grow] * wdeq;
            float* dst = C + (size_t)grow * N + gcol;
            #pragma unroll
            for (int u = 0; u < 8; u++)
                dst[u] = Csw[r * CS_LD + cc + u] * sc + bias[gcol + u];
        }
    }
}

// ---------------- rope + split into per-head chunked q/k/v ----------------
__global__ void __launch_bounds__(256) rope_split(const float* __restrict__ cosb,
                                                  const float* __restrict__ sinb) {
    int idx = blockIdx.x * 256 + threadIdx.x;      // NROWS*NH*32 threads
    int i = idx & 31;
    int tmp = idx >> 5;
    int h = tmp & 15;
    int row = tmp >> 4;
    int b = row >> 13, n = row & 8191;
    int t = n >> 7, r = n & 127;
    const float* src = g_qkv + (size_t)row * QKVN + h * 64 + 2 * i;
    float2 q2 = *(const float2*)(src);
    float2 k2 = *(const float2*)(src + 1024);
    float2 v2 = *(const float2*)(src + 2048);
    float c = cosb[n * 32 + i], s = sinb[n * 32 + i];
    float2 qo = make_float2(q2.x * c - q2.y * s, q2.y * c + q2.x * s);
    float2 ko = make_float2(k2.x * c - k2.y * s, k2.y * c + k2.x * s);
    size_t dst = (((size_t)b * NH + h) * NT + t) * (CHUNK * HD) + r * 64 + 2 * i;
    *(float2*)(g_q + dst) = qo;
    *(float2*)(g_k + dst) = ko;
    *(float2*)(g_v + dst) = v2;
}

// ---------------- intra-chunk attention + chunk KV summary ----------------
#define CPAD 65
#define SPAD 132
__global__ void __launch_bounds__(256) attn_intra() {
    int t = blockIdx.x, h = blockIdx.y, b = blockIdx.z;
    extern __shared__ float sm[];
    float* sQ = sm;                       // 128*65  (later reused for V)
    float* sK = sQ + 128 * CPAD;          // 128*65
    float* sS = sK + 128 * CPAD;          // 128*132
    float* rowsum = sS + 128 * SPAD;      // 128

    size_t base = (((size_t)b * NH + h) * NT + t) * (CHUNK * HD);
    int tid = threadIdx.x;

    #pragma unroll
    for (int u = 0; u < 8; u++) {
        int i = tid + u * 256;            // 0..2047 float4 units
        int r = i >> 4, c4 = (i & 15) * 4;
        float4 qv = *(const float4*)(g_q + base + (size_t)r * 64 + c4);
        float4 kv = *(const float4*)(g_k + base + (size_t)r * 64 + c4);
        sQ[r * CPAD + c4 + 0] = qv.x; sQ[r * CPAD + c4 + 1] = qv.y;
        sQ[r * CPAD + c4 + 2] = qv.z; sQ[r * CPAD + c4 + 3] = qv.w;
        sK[r * CPAD + c4 + 0] = kv.x; sK[r * CPAD + c4 + 1] = kv.y;
        sK[r * CPAD + c4 + 2] = kv.z; sK[r * CPAD + c4 + 3] = kv.w;
    }
    __syncthreads();

    int ty = tid >> 4, tx = tid & 15;
    int R = ty * 8, Cc = tx * 8;
    {
        float acc[8][8];
        #pragma unroll
        for (int i = 0; i < 8; i++)
            #pragma unroll
            for (int j = 0; j < 8; j++) acc[i][j] = 0.f;
        for (int d = 0; d < 64; d++) {
            float qr[8], kr[8];
            #pragma unroll
            for (int i = 0; i < 8; i++) qr[i] = sQ[(R + i) * CPAD + d];
            #pragma unroll
            for (int j = 0; j < 8; j++) kr[j] = sK[(Cc + j) * CPAD + d];
            #pragma unroll
            for (int i = 0; i < 8; i++)
                #pragma unroll
                for (int j = 0; j < 8; j++) acc[i][j] = fmaf(qr[i], kr[j], acc[i][j]);
        }
        #pragma unroll
        for (int i = 0; i < 8; i++)
            #pragma unroll
            for (int j = 0; j < 8; j++)
                sS[(R + i) * SPAD + Cc + j] = acc[i][j] * SCALE_ATTN;
    }
    __syncthreads();

    // prefetch V while doing softmax
    float4 vbuf[8];
    #pragma unroll
    for (int u = 0; u < 8; u++) {
        int i = tid + u * 256;
        int r = i >> 4, c4 = (i & 15) * 4;
        vbuf[u] = *(const float4*)(g_v + base + (size_t)r * 64 + c4);
    }

    {   // softmax: 2 threads per row
        int r = tid >> 1;
        int c0 = (tid & 1) * 64;
        float mx = -3.0e38f;
        for (int c = c0; c < c0 + 64; c++)
            if (c <= r) mx = fmaxf(mx, sS[r * SPAD + c]);
        mx = fmaxf(mx, __shfl_xor_sync(0xffffffffu, mx, 1));
        float sum = 0.f;
        for (int c = c0; c < c0 + 64; c++) {
            float e = (c <= r) ? fexp(sS[r * SPAD + c] - mx) : 0.f;
            sS[r * SPAD + c] = e;
            sum += e;
        }
        sum += __shfl_xor_sync(0xffffffffu, sum, 1);
        if ((tid & 1) == 0) rowsum[r] = sum;
    }
    // store V into sQ (sQ no longer read)
    #pragma unroll
    for (int u = 0; u < 8; u++) {
        int i = tid + u * 256;
        int r = i >> 4, c4 = (i & 15) * 4;
        sQ[r * CPAD + c4 + 0] = vbuf[u].x; sQ[r * CPAD + c4 + 1] = vbuf[u].y;
        sQ[r * CPAD + c4 + 2] = vbuf[u].z; sQ[r * CPAD + c4 + 3] = vbuf[u].w;
    }
    __syncthreads();
    float* sV = sQ;

    // o_intra = softmax(S) @ V : each thread 8 rows x 4 cols
    {
        int C4 = tx * 4;
        float o[8][4];
        #pragma unroll
        for (int i = 0; i < 8; i++)
            #pragma unroll
            for (int j = 0; j < 4; j++) o[i][j] = 0.f;
        for (int kk = 0; kk < 128; kk++) {
            float sreg[8], vreg[4];
            #pragma unroll
            for (int i = 0; i < 8; i++) sreg[i] = sS[(R + i) * SPAD + kk];
            #pragma unroll
            for (int j = 0; j < 4; j++) vreg[j] = sV[kk * CPAD + C4 + j];
            #pragma unroll
            for (int i = 0; i < 8; i++)
                #pragma unroll
                for (int j = 0; j < 4; j++) o[i][j] = fmaf(sreg[i], vreg[j], o[i][j]);
        }
        #pragma unroll
        for (int i = 0; i < 8; i++) {
            float inv = 1.0f / rowsum[R + i];
            size_t grow = (size_t)b * SEQ + (size_t)t * CHUNK + R + i;
            float4 wv = make_float4(o[i][0] * inv, o[i][1] * inv, o[i][2] * inv, o[i][3] * inv);
            *(float4*)(g_attn + grow * DIMC + h * 64 + C4) = wv;
        }
    }

    // S_t = K^T V : thread 4x4 tile over 64x64
    {
        int D = ty * 4, E = tx * 4;
        float acc[4][4];
        #pragma unroll
        for (int i = 0; i < 4; i++)
            #pragma unroll
            for (int j = 0; j < 4; j++) acc[i][j] = 0.f;
        for (int r = 0; r < 128; r++) {
            float kr[4], vr[4];
            #pragma unroll
            for (int i = 0; i < 4; i++) kr[i] = sK[r * CPAD + D + i];
            #pragma unroll
            for (int j = 0; j < 4; j++) vr[j] = sV[r * CPAD + E + j];
            #pragma unroll
            for (int i = 0; i < 4; i++)
                #pragma unroll
                for (int j = 0; j < 4; j++) acc[i][j] = fmaf(kr[i], vr[j], acc[i][j]);
        }
        size_t kb = (((size_t)b * NH + h) * NT + t) * (HD * HD);
        #pragma unroll
        for (int i = 0; i < 4; i++) {
            float4 wv = make_float4(acc[i][0], acc[i][1], acc[i][2], acc[i][3]);
            *(float4*)(g_kvsum + kb + (size_t)(D + i) * 64 + E) = wv;
        }
    }
}

// ---------------- exclusive prefix-sum of chunk KV matrices ----------------
__global__ void __launch_bounds__(256) kv_prefix() {
    int bh = blockIdx.x;
    int tid = threadIdx.x;
    size_t base = (size_t)bh * NT * (HD * HD);
    float acc[16];
    #pragma unroll
    for (int c = 0; c < 16; c++) acc[c] = 0.f;
    for (int t = 0; t < NT; t++) {
        size_t p = base + (size_t)t * (HD * HD);
        #pragma unroll
        for (int c = 0; c < 16; c++) {
            size_t off = p + c * 256 + tid;
            float v = g_kvsum[off];
            g_kvpre[off] = acc[c];
            acc[c] += v;
        }
    }
}

// ---------------- o_inter = q @ kv_prefix, accumulated into g_attn ----------------
__global__ void __launch_bounds__(256) attn_inter() {
    int t = blockIdx.x, h = blockIdx.y, b = blockIdx.z;
    extern __shared__ float sm2[];
    float* sQ  = sm2;              // 128*64
    float* sKV = sm2 + 128 * 64;   // 64*64
    size_t base = (((size_t)b * NH + h) * NT + t) * (CHUNK * HD);
    size_t kb   = (((size_t)b * NH + h) * NT + t) * (HD * HD);
    int tid = threadIdx.x;

    #pragma unroll
    for (int u = 0; u < 8; u++) {
        int i = (tid + u * 256) * 4;
        *(float4*)(sQ + i) = *(const float4*)(g_q + base + i);
    }
    #pragma unroll
    for (int u = 0; u < 4; u++) {
        int i = (tid + u * 256) * 4;
        *(float4*)(sKV + i) = *(const float4*)(g_kvpre + kb + i);
    }
    __syncthreads();

    int ty = tid >> 4, tx = tid & 15;
    int R = ty * 8, C4 = tx * 4;
    float o[8][4];
    #pragma unroll
    for (int i = 0; i < 8; i++)
        #pragma unroll
        for (int j = 0; j < 4; j++) o[i][j] = 0.f;
    for (int d = 0; d < 64; d++) {
        float qr[8], kv[4];
        #pragma unroll
        for (int i = 0; i < 8; i++) qr[i] = sQ[(R + i) * 64 + d];
        #pragma unroll
        for (int j = 0; j < 4; j++) kv[j] = sKV[d * 64 + C4 + j];
        #pragma unroll
        for (int i = 0; i < 8; i++)
            #pragma unroll
            for (int j = 0; j < 4; j++) o[i][j] = fmaf(qr[i], kv[j], o[i][j]);
    }
    #pragma unroll
    for (int i = 0; i < 8; i++) {
        size_t grow = (size_t)b * SEQ + (size_t)t * CHUNK + R + i;
        float* dst = g_attn + grow * DIMC + h * 64 + C4;
        float4 old = *(float4*)dst;
        old.x += o[i][0]; old.y += o[i][1]; old.z += o[i][2]; old.w += o[i][3];
        *(float4*)dst = old;
    }
}

// ---------------- launch ----------------
extern "C" void kernel_launch(void* const* d_in, const int* in_sizes, int n_in,
                              void* d_out, int out_size) {
    const float* x       = (const float*)d_in[0];
    const float* cosb    = (const float*)d_in[1];
    const float* sinb    = (const float*)d_in[2];
    const float* qkv_w   = (const float*)d_in[3];
    const float* qkv_b   = (const float*)d_in[4];
    const float* qkv_nw  = (const float*)d_in[5];
    const float* proj_w  = (const float*)d_in[6];
    const float* proj_b  = (const float*)d_in[7];
    const float* proj_nw = (const float*)d_in[8];
    const float* norm_w  = (const float*)d_in[9];
    float* out = (float*)d_out;

    static bool attr_done = false;
    if (!attr_done) {
        cudaFuncSetAttribute(attn_intra, cudaFuncAttributeMaxDynamicSharedMemorySize,
                             (128 * CPAD * 2 + 128 * SPAD + 128) * sizeof(float));
        cudaFuncSetAttribute(attn_inter, cudaFuncAttributeMaxDynamicSharedMemorySize,
                             (128 * 64 + 64 * 64) * sizeof(float));
        attr_done = true;
    }

    __nv_bfloat16 *xq_p, *wqkv_p, *wproj_p, *xq2_p;
    float *qkv_p, *adeq_p, *adeq2_p;
    cudaGetSymbolAddress((void**)&xq_p,    g_xq);
    cudaGetSymbolAddress((void**)&wqkv_p,  g_wq_qkv);
    cudaGetSymbolAddress((void**)&wproj_p, g_wq_proj);
    cudaGetSymbolAddress((void**)&xq2_p,   g_xq2);
    cudaGetSymbolAddress((void**)&qkv_p,   g_qkv);
    cudaGetSymbolAddress((void**)&adeq_p,  g_adeq);
    cudaGetSymbolAddress((void**)&adeq2_p, g_adeq2);

    // weight quantization
    absmean_partial<<<256, 256>>>(qkv_w, QKVN * DIMC);
    absmean_final<<<1, 256>>>(QKVN * DIMC, 0);
    quant_weight<<<2048, 256>>>(qkv_w, wqkv_p, QKVN * DIMC, 0);
    absmean_partial<<<256, 256>>>(proj_w, DIMC * DIMC);
    absmean_final<<<1, 256>>>(DIMC * DIMC, 1);
    quant_weight<<<2048, 256>>>(proj_w, wproj_p, DIMC * DIMC, 1);

    // QKV bitlinear
    act_quant_x<<<NROWS, 256>>>(x, qkv_nw);
    {
        dim3 grid(QKVN / 64, NROWS / 128);
        gemm_bf16<<<grid, 256>>>(xq_p, wqkv_p, qkv_p, QKVN, adeq_p, 0, qkv_b);
    }

    // rope + split
    rope_split<<<(NROWS * NH * 32) / 256, 256>>>(cosb, sinb);

    // attention
    {
        dim3 grid(NT, NH, BATCH);
        size_t smem = (128 * CPAD * 2 + 128 * SPAD + 128) * sizeof(float);
        attn_intra<<<grid, 256, smem>>>();
    }
    kv_prefix<<<BATCH * NH, 256>>>();
    {
        dim3 grid(NT, NH, BATCH);
        size_t smem = (128 * 64 + 64 * 64) * sizeof(float);
        attn_inter<<<grid, 256, smem>>>();
    }

    // output norm + proj bitlinear
    norm2_quant<<<NROWS, 256>>>(norm_w, proj_nw);
    {
        dim3 grid(DIMC / 64, NROWS / 128);
        gemm_bf16<<<grid, 256>>>(xq2_p, wproj_p, out, DIMC, adeq2_p, 1, proj_b);
    }
}